// round 5
// baseline (speedup 1.0000x reference)
#include <cuda_runtime.h>
#include <math.h>

// YOLOv2 loss: preds/targets (128, 26, 26, 425) fp32 -> scalar fp32.
// 425 = 5 boxes * (5 + 80).
// Warp = 6 cells. Lane = one (cell, box) pair for geometry (30 lanes active).
// Class loss: 8 obj boxes per pass via eight 4-lane groups (masked REDUX),
// 20 classes per lane -> ~2 serial passes per warp, high MLP per pass.

#define B_BOXES 5
#define D_BOX 85
#define CH 425
#define CELLS (128 * 26 * 26)                 // 86528
#define CELLS_PER_WARP 6
#define WARPS_PER_BLOCK 8
#define TOTAL_WARPS ((CELLS + CELLS_PER_WARP - 1) / CELLS_PER_WARP)          // 14422
#define NUM_BLOCKS ((TOTAL_WARPS + WARPS_PER_BLOCK - 1) / WARPS_PER_BLOCK)   // 1803
#define FULL 0xffffffffu

__global__ void zero_out_kernel(float* out) { out[0] = 0.0f; }

__device__ __forceinline__ unsigned okey(float f) {
    unsigned u = __float_as_uint(f);
    return (u & 0x80000000u) ? ~u : (u | 0x80000000u);
}

__global__ void __launch_bounds__(256) yolo_loss_kernel(
    const float* __restrict__ preds,
    const float* __restrict__ targets,
    float* __restrict__ out)
{
    __shared__ float blocksum[WARPS_PER_BLOCK];

    const int warp = threadIdx.x >> 5;
    const int lane = threadIdx.x & 31;
    const int gwarp = blockIdx.x * WARPS_PER_BLOCK + warp;
    const int base_cell = gwarp * CELLS_PER_WARP;

    // ---- Geometry: lane -> (cell, box) ----
    const int c_local = lane / 5;                  // lanes 30,31 -> 6 (guarded)
    const int b = lane - c_local * 5;
    const int cell = base_cell + c_local;
    const bool valid = (lane < 30) && (cell < CELLS);
    const float validf = valid ? 1.0f : 0.0f;
    const int cc = (cell < CELLS) ? cell : (CELLS - 1);  // clamp: loads in-bounds

    const size_t hoff = (size_t)cc * CH + b * D_BOX;
    const float* __restrict__ ph = preds + hoff;
    const float* __restrict__ th = targets + hoff;
    const float p0 = ph[0], p1 = ph[1], p2 = ph[2], p3 = ph[3], p4 = ph[4];
    const float t0 = th[0], t1 = th[1], t2 = th[2], t3 = th[3], t4 = th[4];

    const float px1 = p0 - p2 * 0.5f, py1 = p1 - p3 * 0.5f;
    const float px2 = p0 + p2 * 0.5f, py2 = p1 + p3 * 0.5f;
    const float area_p = (px2 - px1) * (py2 - py1);

    float best = -INFINITY;
    int bestj = 0;
    #pragma unroll
    for (int j = 0; j < B_BOXES; j++) {
        const int src = lane - b + j;   // lane holding target box j of my cell
        const float tx  = __shfl_sync(FULL, t0, src);
        const float ty  = __shfl_sync(FULL, t1, src);
        const float tw  = __shfl_sync(FULL, t2, src);
        const float thh = __shfl_sync(FULL, t3, src);
        const float tx1 = tx - tw * 0.5f, ty1 = ty - thh * 0.5f;
        const float tx2 = tx + tw * 0.5f, ty2 = ty + thh * 0.5f;
        float iw = fminf(px2, tx2) - fmaxf(px1, tx1); iw = fmaxf(iw, 0.0f);
        float ih = fminf(py2, ty2) - fmaxf(py1, ty1); ih = fmaxf(ih, 0.0f);
        const float inter = iw * ih;
        const float at = (tx2 - tx1) * (ty2 - ty1);
        const float iou = inter / (area_p + at - inter + 1e-6f);
        if (iou > best) { best = iou; bestj = j; }   // strict >: first max
    }
    const int src2 = lane - b + bestj;
    const float m0 = __shfl_sync(FULL, t0, src2);
    const float m1 = __shfl_sync(FULL, t1, src2);
    const float m2 = __shfl_sync(FULL, t2, src2);
    const float m3 = __shfl_sync(FULL, t3, src2);
    const float m4 = __shfl_sync(FULL, t4, src2);
    const float mobj = (m4 > 0.0f) ? 1.0f : 0.0f;

    float acc;
    {
        const float dx = p0 - m0, dy = p1 - m1;
        const float lxy = 5.0f * mobj * (dx * dx + dy * dy);
        const float pws = sqrtf(fabsf(p2 + 1e-6f));
        const float phs = sqrtf(fabsf(p3 + 1e-6f));
        const float tws = sqrtf(fabsf(m2 + 1e-6f));
        const float ths = sqrtf(fabsf(m3 + 1e-6f));
        const float dw = pws - tws, dh = phs - ths;
        const float lwh = 5.0f * mobj * (dw * dw + dh * dh);
        const float dc = p4 - m4, cs = dc * dc;
        const float lcf = mobj * cs + 0.5f * (1.0f - mobj) * cs;
        acc = validf * (lxy + lwh + lcf);
    }

    // ---- Class loss: 8 obj boxes per pass, 4-lane groups ----
    unsigned mask = __ballot_sync(FULL, valid && (m4 > 0.0f));  // bits 0..29
    const int grp = lane >> 2;          // 0..7
    const int gl = lane & 3;            // 0..3
    const unsigned gmask = 0xFu << (grp * 4);

    while (mask) {
        // group's box = (grp+1)-th set bit; -1 if fewer than grp+1 remain
        const int gi = __fns(mask, 0, grp + 1);
        // clear lowest 8 set bits for next pass
        const int p9 = __fns(mask, 0, 9);
        mask = (p9 < 0) ? 0u : (mask & (0xFFFFFFFFu << p9));

        const bool gv = (gi >= 0);
        const int box = gv ? gi : 0;    // dummy box 0 always in-bounds
        const int cl2 = box / 5;
        const int b2 = box - cl2 * 5;
        const size_t off = (size_t)(base_cell + cl2) * CH + b2 * D_BOX + 5;
        const float* __restrict__ pp = preds + off;
        const float* __restrict__ tp = targets + off;

        // 20 classes per lane: gl, gl+4, ..., gl+76 (ascending indices)
        float es = 0.0f;
        float bv = -INFINITY;
        int bi = 0;
        #pragma unroll
        for (int k = 0; k < 20; k++) {
            es += __expf(pp[gl + 4 * k]);
            const float tv = tp[gl + 4 * k];
            if (tv > bv) { bv = tv; bi = gl + 4 * k; }
        }

        // group sum of exp via 16.16 fixed point REDUX.ADD
        const int q = __float2int_rn(es * 65536.0f);
        const int qs = __reduce_add_sync(gmask, q);

        // group argmax with exact first-occurrence tie-break
        const unsigned key = okey(bv);
        const unsigned kmax = __reduce_max_sync(gmask, key);
        const int cand = (key == kmax) ? bi : 127;
        const int gbi = __reduce_min_sync(gmask, cand);

        if (gv && gl == 0) {
            const float pval = __ldg(pp + gbi);   // single L1-hot load of p[tcls]
            acc += __logf((float)qs * (1.0f / 65536.0f)) - pval;
        }
    }

    // ---- Reduction: warp -> block -> global atomic ----
    #pragma unroll
    for (int o = 16; o > 0; o >>= 1)
        acc += __shfl_xor_sync(FULL, acc, o);
    if (lane == 0) blocksum[warp] = acc;
    __syncthreads();
    if (threadIdx.x == 0) {
        float s = 0.0f;
        #pragma unroll
        for (int w = 0; w < WARPS_PER_BLOCK; w++) s += blocksum[w];
        atomicAdd(out, s);
    }
}

extern "C" void kernel_launch(void* const* d_in, const int* in_sizes, int n_in,
                              void* d_out, int out_size)
{
    const float* preds   = (const float*)d_in[0];
    const float* targets = (const float*)d_in[1];
    float* out = (float*)d_out;

    zero_out_kernel<<<1, 1>>>(out);
    yolo_loss_kernel<<<NUM_BLOCKS, 256>>>(preds, targets, out);
}

// round 6
// speedup vs baseline: 1.2309x; 1.2309x over previous
#include <cuda_runtime.h>
#include <math.h>

// YOLOv2 loss: preds/targets (128, 26, 26, 425) fp32 -> scalar fp32.
// 425 = 5 boxes * (5 + 80).
// Warp = 6 cells. Lane = one (cell, box) pair for geometry (30 lanes active).
// Class loss: four 8-lane groups (sector-perfect: 8 lanes x 4B = 32B), each
// group processes TWO obj boxes per pass -> 8 boxes/pass, ~2 serial passes.

#define B_BOXES 5
#define D_BOX 85
#define CH 425
#define CELLS (128 * 26 * 26)                 // 86528
#define CELLS_PER_WARP 6
#define WARPS_PER_BLOCK 8
#define TOTAL_WARPS ((CELLS + CELLS_PER_WARP - 1) / CELLS_PER_WARP)          // 14422
#define NUM_BLOCKS ((TOTAL_WARPS + WARPS_PER_BLOCK - 1) / WARPS_PER_BLOCK)   // 1803
#define FULL 0xffffffffu

__global__ void zero_out_kernel(float* out) { out[0] = 0.0f; }

__device__ __forceinline__ unsigned okey(float f) {
    unsigned u = __float_as_uint(f);
    return (u & 0x80000000u) ? ~u : (u | 0x80000000u);
}

__global__ void __launch_bounds__(256) yolo_loss_kernel(
    const float* __restrict__ preds,
    const float* __restrict__ targets,
    float* __restrict__ out)
{
    __shared__ float blocksum[WARPS_PER_BLOCK];

    const int warp = threadIdx.x >> 5;
    const int lane = threadIdx.x & 31;
    const int gwarp = blockIdx.x * WARPS_PER_BLOCK + warp;
    const int base_cell = gwarp * CELLS_PER_WARP;

    // ---- Geometry: lane -> (cell, box) ----
    const int c_local = lane / 5;                  // lanes 30,31 -> 6 (guarded)
    const int b = lane - c_local * 5;
    const int cell = base_cell + c_local;
    const bool valid = (lane < 30) && (cell < CELLS);
    const float validf = valid ? 1.0f : 0.0f;
    const int cc = (cell < CELLS) ? cell : (CELLS - 1);  // clamp: loads in-bounds

    const size_t hoff = (size_t)cc * CH + b * D_BOX;
    const float* __restrict__ ph = preds + hoff;
    const float* __restrict__ th = targets + hoff;
    const float p0 = ph[0], p1 = ph[1], p2 = ph[2], p3 = ph[3], p4 = ph[4];
    const float t0 = th[0], t1 = th[1], t2 = th[2], t3 = th[3], t4 = th[4];

    const float px1 = p0 - p2 * 0.5f, py1 = p1 - p3 * 0.5f;
    const float px2 = p0 + p2 * 0.5f, py2 = p1 + p3 * 0.5f;
    const float area_p = (px2 - px1) * (py2 - py1);

    float best = -INFINITY;
    int bestj = 0;
    #pragma unroll
    for (int j = 0; j < B_BOXES; j++) {
        const int src = lane - b + j;   // lane holding target box j of my cell
        const float tx  = __shfl_sync(FULL, t0, src);
        const float ty  = __shfl_sync(FULL, t1, src);
        const float tw  = __shfl_sync(FULL, t2, src);
        const float thh = __shfl_sync(FULL, t3, src);
        const float tx1 = tx - tw * 0.5f, ty1 = ty - thh * 0.5f;
        const float tx2 = tx + tw * 0.5f, ty2 = ty + thh * 0.5f;
        float iw = fminf(px2, tx2) - fmaxf(px1, tx1); iw = fmaxf(iw, 0.0f);
        float ih = fminf(py2, ty2) - fmaxf(py1, ty1); ih = fmaxf(ih, 0.0f);
        const float inter = iw * ih;
        const float at = (tx2 - tx1) * (ty2 - ty1);
        const float iou = inter / (area_p + at - inter + 1e-6f);
        if (iou > best) { best = iou; bestj = j; }   // strict >: first max
    }
    const int src2 = lane - b + bestj;
    const float m0 = __shfl_sync(FULL, t0, src2);
    const float m1 = __shfl_sync(FULL, t1, src2);
    const float m2 = __shfl_sync(FULL, t2, src2);
    const float m3 = __shfl_sync(FULL, t3, src2);
    const float m4 = __shfl_sync(FULL, t4, src2);
    const float mobj = (m4 > 0.0f) ? 1.0f : 0.0f;

    float acc;
    {
        const float dx = p0 - m0, dy = p1 - m1;
        const float lxy = 5.0f * mobj * (dx * dx + dy * dy);
        const float pws = sqrtf(fabsf(p2 + 1e-6f));
        const float phs = sqrtf(fabsf(p3 + 1e-6f));
        const float tws = sqrtf(fabsf(m2 + 1e-6f));
        const float ths = sqrtf(fabsf(m3 + 1e-6f));
        const float dw = pws - tws, dh = phs - ths;
        const float lwh = 5.0f * mobj * (dw * dw + dh * dh);
        const float dc = p4 - m4, cs = dc * dc;
        const float lcf = mobj * cs + 0.5f * (1.0f - mobj) * cs;
        acc = validf * (lxy + lwh + lcf);
    }

    // ---- Class loss: 8 obj boxes per pass (4 groups x 2 boxes) ----
    unsigned mask = __ballot_sync(FULL, valid && (m4 > 0.0f));  // bits 0..29
    const int grp = lane >> 3;          // 0..3
    const int gl = lane & 7;            // 0..7
    const unsigned gmask = 0xFFu << (grp * 8);

    while (mask) {
        // group's two boxes: (grp+1)-th and (grp+5)-th set bits (-1 if absent)
        const int giA = __fns(mask, 0, grp + 1);
        const int giB = __fns(mask, 0, grp + 5);
        // clear lowest 8 set bits for next pass
        const int p9 = __fns(mask, 0, 9);
        mask = (p9 < 0) ? 0u : (mask & (0xFFFFFFFFu << p9));

        const bool gvA = (giA >= 0);
        const bool gvB = (giB >= 0);
        const int boxA = gvA ? giA : 0;   // dummy box 0 always in-bounds
        const int boxB = gvB ? giB : 0;
        const int clA = boxA / 5, bA = boxA - clA * 5;
        const int clB = boxB / 5, bB = boxB - clB * 5;
        const size_t offA = (size_t)(base_cell + clA) * CH + bA * D_BOX + 5;
        const size_t offB = (size_t)(base_cell + clB) * CH + bB * D_BOX + 5;
        const float* __restrict__ ppA = preds + offA;
        const float* __restrict__ tpA = targets + offA;
        const float* __restrict__ ppB = preds + offB;
        const float* __restrict__ tpB = targets + offB;

        // 10 classes per lane per box: gl, gl+8, ..., gl+72 (ascending)
        float esA = 0.0f, esB = 0.0f;
        float bvA = -INFINITY, bvB = -INFINITY;
        int biA = 0, biB = 0;
        #pragma unroll
        for (int k = 0; k < 10; k++) {
            const int idx = gl + 8 * k;
            esA += __expf(ppA[idx]);
            esB += __expf(ppB[idx]);
            const float tvA = tpA[idx];
            const float tvB = tpB[idx];
            if (tvA > bvA) { bvA = tvA; biA = idx; }
            if (tvB > bvB) { bvB = tvB; biB = idx; }
        }

        // group sums of exp via 16.16 fixed point REDUX.ADD
        const int qA = __float2int_rn(esA * 65536.0f);
        const int qB = __float2int_rn(esB * 65536.0f);
        const int qsA = __reduce_add_sync(gmask, qA);
        const int qsB = __reduce_add_sync(gmask, qB);

        // group argmax with exact first-occurrence tie-break
        const unsigned keyA = okey(bvA);
        const unsigned keyB = okey(bvB);
        const unsigned kmA = __reduce_max_sync(gmask, keyA);
        const unsigned kmB = __reduce_max_sync(gmask, keyB);
        const int candA = (keyA == kmA) ? biA : 127;
        const int candB = (keyB == kmB) ? biB : 127;
        const int gbiA = __reduce_min_sync(gmask, candA);
        const int gbiB = __reduce_min_sync(gmask, candB);

        if (gl == 0) {
            if (gvA) {
                const float pvalA = __ldg(ppA + gbiA);
                acc += __logf((float)qsA * (1.0f / 65536.0f)) - pvalA;
            }
            if (gvB) {
                const float pvalB = __ldg(ppB + gbiB);
                acc += __logf((float)qsB * (1.0f / 65536.0f)) - pvalB;
            }
        }
    }

    // ---- Reduction: warp -> block -> global atomic ----
    #pragma unroll
    for (int o = 16; o > 0; o >>= 1)
        acc += __shfl_xor_sync(FULL, acc, o);
    if (lane == 0) blocksum[warp] = acc;
    __syncthreads();
    if (threadIdx.x == 0) {
        float s = 0.0f;
        #pragma unroll
        for (int w = 0; w < WARPS_PER_BLOCK; w++) s += blocksum[w];
        atomicAdd(out, s);
    }
}

extern "C" void kernel_launch(void* const* d_in, const int* in_sizes, int n_in,
                              void* d_out, int out_size)
{
    const float* preds   = (const float*)d_in[0];
    const float* targets = (const float*)d_in[1];
    float* out = (float*)d_out;

    zero_out_kernel<<<1, 1>>>(out);
    yolo_loss_kernel<<<NUM_BLOCKS, 256>>>(preds, targets, out);
}

// round 7
// speedup vs baseline: 1.2737x; 1.0347x over previous
#include <cuda_runtime.h>
#include <math.h>

// YOLOv2 loss, two-phase:
//   zero_kernel: clears scalar out + worklist counter.
//   geo_kernel : warp = 6 cells; smem-staged headers; IoU match; xy/wh/conf
//                losses; appends obj-box global ids to g_list (warp-agg atomic).
//   cls_kernel : warp = one obj box; coalesced 80-class log-softmax + target
//                argmax via full-warp REDUX; accumulates class NLL.

#define B_BOXES 5
#define D_BOX 85
#define CH 425
#define CELLS (128 * 26 * 26)                 // 86528
#define CELLS_PER_WARP 6
#define WARPS_PER_BLOCK 8
#define TOTAL_WARPS ((CELLS + CELLS_PER_WARP - 1) / CELLS_PER_WARP)            // 14422
#define NUM_BLOCKS_A ((TOTAL_WARPS + WARPS_PER_BLOCK - 1) / WARPS_PER_BLOCK)   // 1803
#define NUM_BLOCKS_B 2368
#define FULL 0xffffffffu
#define MAX_BOXES (CELLS * B_BOXES)           // 432640

__device__ int g_count;
__device__ int g_list[MAX_BOXES];

__global__ void zero_kernel(float* out) { out[0] = 0.0f; g_count = 0; }

__device__ __forceinline__ unsigned okey(float f) {
    unsigned u = __float_as_uint(f);
    return (u & 0x80000000u) ? ~u : (u | 0x80000000u);
}

// ---------------- Kernel A: geometry + compaction ----------------
__global__ void __launch_bounds__(256) geo_kernel(
    const float* __restrict__ preds,
    const float* __restrict__ targets,
    float* __restrict__ out)
{
    __shared__ float sp[WARPS_PER_BLOCK][CELLS_PER_WARP][25];
    __shared__ float st[WARPS_PER_BLOCK][CELLS_PER_WARP][25];
    __shared__ float blocksum[WARPS_PER_BLOCK];

    const int warp = threadIdx.x >> 5;
    const int lane = threadIdx.x & 31;
    const int gwarp = blockIdx.x * WARPS_PER_BLOCK + warp;
    const int base_cell = gwarp * CELLS_PER_WARP;

    // Stage headers: one cell per LDG (7 sectors/LDG instead of 30).
    const int hb = lane / 5;               // box (lanes 0..24)
    const int he = lane - hb * 5;          // element
    #pragma unroll
    for (int c = 0; c < CELLS_PER_WARP; c++) {
        const int cellc = base_cell + c;
        const int ccl = (cellc < CELLS) ? cellc : (CELLS - 1);
        const size_t o = (size_t)ccl * CH + hb * D_BOX + he;
        if (lane < 25) {
            sp[warp][c][lane] = preds[o];
            st[warp][c][lane] = targets[o];
        }
    }
    __syncwarp();

    // Geometry: lane = (cell, box); 30 lanes active.
    const int c_local = lane / 5;
    const int cl = (c_local < CELLS_PER_WARP) ? c_local : (CELLS_PER_WARP - 1);
    const int b = lane - c_local * 5;
    const int cell = base_cell + c_local;
    const bool valid = (lane < 30) && (cell < CELLS);
    const float validf = valid ? 1.0f : 0.0f;

    const float* p = &sp[warp][cl][b * 5];
    const float p0 = p[0], p1 = p[1], p2 = p[2], p3 = p[3], p4 = p[4];

    const float px1 = p0 - p2 * 0.5f, py1 = p1 - p3 * 0.5f;
    const float px2 = p0 + p2 * 0.5f, py2 = p1 + p3 * 0.5f;
    const float area_p = (px2 - px1) * (py2 - py1);

    float best = -INFINITY;
    int bestj = 0;
    #pragma unroll
    for (int j = 0; j < B_BOXES; j++) {
        const float* t = &st[warp][cl][j * 5];
        const float tx = t[0], ty = t[1], tw = t[2], thh = t[3];
        const float tx1 = tx - tw * 0.5f, ty1 = ty - thh * 0.5f;
        const float tx2 = tx + tw * 0.5f, ty2 = ty + thh * 0.5f;
        float iw = fminf(px2, tx2) - fmaxf(px1, tx1); iw = fmaxf(iw, 0.0f);
        float ih = fminf(py2, ty2) - fmaxf(py1, ty1); ih = fmaxf(ih, 0.0f);
        const float inter = iw * ih;
        const float at = (tx2 - tx1) * (ty2 - ty1);
        const float iou = inter / (area_p + at - inter + 1e-6f);
        if (iou > best) { best = iou; bestj = j; }    // strict >: first max
    }
    const float* m = &st[warp][cl][bestj * 5];
    const float m0 = m[0], m1 = m[1], m2 = m[2], m3 = m[3], m4 = m[4];
    const float mobj = (m4 > 0.0f) ? 1.0f : 0.0f;

    float acc;
    {
        const float dx = p0 - m0, dy = p1 - m1;
        const float lxy = 5.0f * mobj * (dx * dx + dy * dy);
        const float pws = sqrtf(fabsf(p2 + 1e-6f));
        const float phs = sqrtf(fabsf(p3 + 1e-6f));
        const float tws = sqrtf(fabsf(m2 + 1e-6f));
        const float ths = sqrtf(fabsf(m3 + 1e-6f));
        const float dw = pws - tws, dh = phs - ths;
        const float lwh = 5.0f * mobj * (dw * dw + dh * dh);
        const float dc = p4 - m4, cs = dc * dc;
        const float lcf = mobj * cs + 0.5f * (1.0f - mobj) * cs;
        acc = validf * (lxy + lwh + lcf);
    }

    // Compaction: append obj-box global ids (cell*5 + b) to g_list.
    const bool is_obj = valid && (m4 > 0.0f);
    const unsigned om = __ballot_sync(FULL, is_obj);
    const int n = __popc(om);
    int basep = 0;
    if (lane == 0 && n > 0) basep = atomicAdd(&g_count, n);
    basep = __shfl_sync(FULL, basep, 0);
    if (is_obj) {
        const int rank = __popc(om & ((1u << lane) - 1u));
        g_list[basep + rank] = cell * 5 + b;
    }

    // Reduce geo loss: warp -> block -> global atomic.
    #pragma unroll
    for (int o = 16; o > 0; o >>= 1)
        acc += __shfl_xor_sync(FULL, acc, o);
    if (lane == 0) blocksum[warp] = acc;
    __syncthreads();
    if (threadIdx.x == 0) {
        float s = 0.0f;
        #pragma unroll
        for (int w = 0; w < WARPS_PER_BLOCK; w++) s += blocksum[w];
        atomicAdd(out, s);
    }
}

// ---------------- Kernel B: class loss over compacted boxes ----------------
__global__ void __launch_bounds__(256) cls_kernel(
    const float* __restrict__ preds,
    const float* __restrict__ targets,
    float* __restrict__ out)
{
    __shared__ float blocksum[WARPS_PER_BLOCK];

    const int warp = threadIdx.x >> 5;
    const int lane = threadIdx.x & 31;
    const int gw = blockIdx.x * WARPS_PER_BLOCK + warp;
    const int nwarps = NUM_BLOCKS_B * WARPS_PER_BLOCK;
    const int total = g_count;

    float acc = 0.0f;   // only lane 0 accumulates

    for (int i = gw; i < total; i += nwarps) {
        const int gi = g_list[i];
        const size_t off = (size_t)gi * D_BOX + 5;     // gi*85+5: class vector
        const float* __restrict__ pp = preds + off;
        const float* __restrict__ tp = targets + off;

        // 80 classes over 32 lanes: {lane, lane+32, lane+64 (lanes 0-15)}.
        const float v0 = pp[lane];
        const float v1 = pp[lane + 32];
        const float v2 = (lane < 16) ? pp[lane + 64] : 0.0f;

        float es = __expf(v0) + __expf(v1);
        if (lane < 16) es += __expf(v2);
        const int q = __float2int_rn(es * 65536.0f);
        const int qs = __reduce_add_sync(FULL, q);

        // target argmax, exact first-occurrence tie-break
        float bv = tp[lane];
        int bi = lane;
        {
            const float t1v = tp[lane + 32];
            if (t1v > bv) { bv = t1v; bi = lane + 32; }
            if (lane < 16) {
                const float t2v = tp[lane + 64];
                if (t2v > bv) { bv = t2v; bi = lane + 64; }
            }
        }
        const unsigned key = okey(bv);
        const unsigned km = __reduce_max_sync(FULL, key);
        const int cand = (key == km) ? bi : 127;
        const int gbi = __reduce_min_sync(FULL, cand);

        // pred logit at target class: register select + one shuffle
        const float psel = (gbi < 32) ? v0 : ((gbi < 64) ? v1 : v2);
        const float pval = __shfl_sync(FULL, psel, gbi & 31);

        if (lane == 0)
            acc += __logf((float)qs * (1.0f / 65536.0f)) - pval;
    }

    if (lane == 0) blocksum[warp] = acc;
    __syncthreads();
    if (threadIdx.x == 0) {
        float s = 0.0f;
        #pragma unroll
        for (int w = 0; w < WARPS_PER_BLOCK; w++) s += blocksum[w];
        if (s != 0.0f) atomicAdd(out, s);
    }
}

extern "C" void kernel_launch(void* const* d_in, const int* in_sizes, int n_in,
                              void* d_out, int out_size)
{
    const float* preds   = (const float*)d_in[0];
    const float* targets = (const float*)d_in[1];
    float* out = (float*)d_out;

    zero_kernel<<<1, 1>>>(out);
    geo_kernel<<<NUM_BLOCKS_A, 256>>>(preds, targets, out);
    cls_kernel<<<NUM_BLOCKS_B, 256>>>(preds, targets, out);
}